// round 1
// baseline (speedup 1.0000x reference)
#include <cuda_runtime.h>
#include <math.h>

#define N_NODES 100000
#define N_EDGES 1600000
#define IN_DIM 768
#define HIDDEN 256
#define N_CLASSES 3

// ---- device scratch (static; no allocation allowed) ----
__device__ float g_deg[N_NODES];
__device__ float g_dinv[N_NODES];
__device__ float g_h[(size_t)N_NODES * HIDDEN];    // h' = dinv[i] * (x@W1)[i]
__device__ float g_agg[(size_t)N_NODES * HIDDEN];  // running sum, init = h' (self loop)

// ---------------------------------------------------------------------------
// K0: init degrees to 1.0 (self-loop included)
// ---------------------------------------------------------------------------
__global__ void k_init_deg(int n) {
    int i = blockIdx.x * blockDim.x + threadIdx.x;
    if (i < n) g_deg[i] = 1.0f;
}

// ---------------------------------------------------------------------------
// K1: histogram destination degrees
// ---------------------------------------------------------------------------
__global__ void k_deg(const int* __restrict__ dst, int E) {
    int i = blockIdx.x * blockDim.x + threadIdx.x;
    if (i < E) atomicAdd(&g_deg[dst[i]], 1.0f);
}

// ---------------------------------------------------------------------------
// K2: dinv = rsqrt(deg)   (deg >= 1 always)
// ---------------------------------------------------------------------------
__global__ void k_dinv(int n) {
    int i = blockIdx.x * blockDim.x + threadIdx.x;
    if (i < n) g_dinv[i] = rsqrtf(g_deg[i]);
}

// ---------------------------------------------------------------------------
// K3: tiled fp32 GEMM  h' = dinv[row] * (x @ W1), written to g_h AND g_agg
//   BM=64, BN=64, BK=16, 16x16 threads, 4x4 microtile
// ---------------------------------------------------------------------------
#define BM 64
#define BN 64
#define BK 16

__global__ __launch_bounds__(256, 4) void k_gemm1(const float* __restrict__ x,
                                                  const float* __restrict__ W1,
                                                  int n) {
    __shared__ float As[BK][BM];   // A transposed: As[k][m]
    __shared__ float Bs[BK][BN];

    const int tx = threadIdx.x;    // 0..15
    const int ty = threadIdx.y;    // 0..15
    const int tid = ty * 16 + tx;  // 0..255
    const int row0 = blockIdx.y * BM;
    const int col0 = blockIdx.x * BN;

    // A-tile load mapping: one float4 per thread
    const int a_m = tid >> 2;          // 0..63
    const int a_k4 = (tid & 3) * 4;    // 0,4,8,12
    // B-tile load mapping: one float4 per thread
    const int b_k = tid >> 4;          // 0..15
    const int b_n4 = (tid & 15) * 4;   // 0..60

    float acc[4][4];
#pragma unroll
    for (int i = 0; i < 4; i++)
#pragma unroll
        for (int j = 0; j < 4; j++) acc[i][j] = 0.0f;

    const int a_row = row0 + a_m;
    const bool a_ok = (a_row < n);

    for (int k0 = 0; k0 < IN_DIM; k0 += BK) {
        // load A tile (64 x 16), transpose into As[k][m]
        float4 va = make_float4(0.f, 0.f, 0.f, 0.f);
        if (a_ok) va = *reinterpret_cast<const float4*>(x + (size_t)a_row * IN_DIM + k0 + a_k4);
        As[a_k4 + 0][a_m] = va.x;
        As[a_k4 + 1][a_m] = va.y;
        As[a_k4 + 2][a_m] = va.z;
        As[a_k4 + 3][a_m] = va.w;
        // load B tile (16 x 64)
        float4 vb = *reinterpret_cast<const float4*>(W1 + (size_t)(k0 + b_k) * HIDDEN + col0 + b_n4);
        *reinterpret_cast<float4*>(&Bs[b_k][b_n4]) = vb;
        __syncthreads();

#pragma unroll
        for (int k = 0; k < BK; k++) {
            float4 ra = *reinterpret_cast<const float4*>(&As[k][ty * 4]);
            float4 rb = *reinterpret_cast<const float4*>(&Bs[k][tx * 4]);
            float a0 = ra.x, a1 = ra.y, a2 = ra.z, a3 = ra.w;
            acc[0][0] += a0 * rb.x; acc[0][1] += a0 * rb.y; acc[0][2] += a0 * rb.z; acc[0][3] += a0 * rb.w;
            acc[1][0] += a1 * rb.x; acc[1][1] += a1 * rb.y; acc[1][2] += a1 * rb.z; acc[1][3] += a1 * rb.w;
            acc[2][0] += a2 * rb.x; acc[2][1] += a2 * rb.y; acc[2][2] += a2 * rb.z; acc[2][3] += a2 * rb.w;
            acc[3][0] += a3 * rb.x; acc[3][1] += a3 * rb.y; acc[3][2] += a3 * rb.z; acc[3][3] += a3 * rb.w;
        }
        __syncthreads();
    }

#pragma unroll
    for (int i = 0; i < 4; i++) {
        int row = row0 + ty * 4 + i;
        if (row >= n) continue;
        float s = g_dinv[row];
        float4 v;
        v.x = acc[i][0] * s; v.y = acc[i][1] * s; v.z = acc[i][2] * s; v.w = acc[i][3] * s;
        size_t off = (size_t)row * HIDDEN + col0 + tx * 4;
        *reinterpret_cast<float4*>(g_h + off) = v;
        *reinterpret_cast<float4*>(g_agg + off) = v;   // self-loop contribution
    }
}

// ---------------------------------------------------------------------------
// K4: edge scatter: g_agg[dst] += g_h[src]   (vector f32x4 reductions)
//   one thread per (edge, 4-col chunk): 64 chunks/edge
// ---------------------------------------------------------------------------
__global__ __launch_bounds__(256) void k_scatter(const int* __restrict__ src,
                                                 const int* __restrict__ dst,
                                                 int E) {
    long long t = (long long)blockIdx.x * 256 + threadIdx.x;
    int e = (int)(t >> 6);
    int c = (int)(t & 63);
    if (e >= E) return;
    int s = __ldg(&src[e]);
    int d = __ldg(&dst[e]);
    float4 v = *reinterpret_cast<const float4*>(g_h + (size_t)s * HIDDEN + c * 4);
    float* ap = g_agg + (size_t)d * HIDDEN + c * 4;
    asm volatile("red.global.add.v4.f32 [%0], {%1, %2, %3, %4};"
                 :: "l"(ap), "f"(v.x), "f"(v.y), "f"(v.z), "f"(v.w)
                 : "memory");
}

// ---------------------------------------------------------------------------
// K5: finalize: logits = relu(dinv[i]*agg[i] + b1) @ W2 + b2 -> log_softmax
//   one warp per node
// ---------------------------------------------------------------------------
__global__ __launch_bounds__(256) void k_final(const float* __restrict__ b1,
                                               const float* __restrict__ W2,
                                               const float* __restrict__ b2,
                                               float* __restrict__ out,
                                               int n) {
    __shared__ float sW2[HIDDEN * N_CLASSES];
    __shared__ float sb1[HIDDEN];
    for (int i = threadIdx.x; i < HIDDEN * N_CLASSES; i += blockDim.x) sW2[i] = W2[i];
    for (int i = threadIdx.x; i < HIDDEN; i += blockDim.x) sb1[i] = b1[i];
    __syncthreads();

    int gwarp = (blockIdx.x * blockDim.x + threadIdx.x) >> 5;
    int lane = threadIdx.x & 31;
    if (gwarp >= n) return;

    float di = g_dinv[gwarp];
    const float4* ap = reinterpret_cast<const float4*>(g_agg + (size_t)gwarp * HIDDEN);

    float acc0 = 0.f, acc1 = 0.f, acc2 = 0.f;
#pragma unroll
    for (int cc = 0; cc < 2; cc++) {
        int c = lane + cc * 32;           // float4 index 0..63
        float4 v = ap[c];
        int base = c * 4;
        float h0 = fmaxf(fmaf(di, v.x, sb1[base + 0]), 0.f);
        float h1 = fmaxf(fmaf(di, v.y, sb1[base + 1]), 0.f);
        float h2 = fmaxf(fmaf(di, v.z, sb1[base + 2]), 0.f);
        float h3 = fmaxf(fmaf(di, v.w, sb1[base + 3]), 0.f);
        acc0 += h0 * sW2[(base + 0) * 3 + 0] + h1 * sW2[(base + 1) * 3 + 0]
              + h2 * sW2[(base + 2) * 3 + 0] + h3 * sW2[(base + 3) * 3 + 0];
        acc1 += h0 * sW2[(base + 0) * 3 + 1] + h1 * sW2[(base + 1) * 3 + 1]
              + h2 * sW2[(base + 2) * 3 + 1] + h3 * sW2[(base + 3) * 3 + 1];
        acc2 += h0 * sW2[(base + 0) * 3 + 2] + h1 * sW2[(base + 1) * 3 + 2]
              + h2 * sW2[(base + 2) * 3 + 2] + h3 * sW2[(base + 3) * 3 + 2];
    }
#pragma unroll
    for (int o = 16; o > 0; o >>= 1) {
        acc0 += __shfl_down_sync(0xFFFFFFFFu, acc0, o);
        acc1 += __shfl_down_sync(0xFFFFFFFFu, acc1, o);
        acc2 += __shfl_down_sync(0xFFFFFFFFu, acc2, o);
    }
    if (lane == 0) {
        float l0 = acc0 + b2[0];
        float l1 = acc1 + b2[1];
        float l2 = acc2 + b2[2];
        float m = fmaxf(l0, fmaxf(l1, l2));
        float se = expf(l0 - m) + expf(l1 - m) + expf(l2 - m);
        float lse = m + logf(se);
        out[(size_t)gwarp * 3 + 0] = l0 - lse;
        out[(size_t)gwarp * 3 + 1] = l1 - lse;
        out[(size_t)gwarp * 3 + 2] = l2 - lse;
    }
}

// ---------------------------------------------------------------------------
extern "C" void kernel_launch(void* const* d_in, const int* in_sizes, int n_in,
                              void* d_out, int out_size) {
    const float* x  = (const float*)d_in[0];
    const int*   ei = (const int*)d_in[1];
    const float* W1 = (const float*)d_in[2];
    const float* b1 = (const float*)d_in[3];
    const float* W2 = (const float*)d_in[4];
    const float* b2 = (const float*)d_in[5];
    float* out = (float*)d_out;

    int n = in_sizes[0] / IN_DIM;
    int E = in_sizes[1] / 2;
    const int* src = ei;
    const int* dst = ei + E;

    // K0/K1/K2: degree normalization
    k_init_deg<<<(n + 255) / 256, 256>>>(n);
    k_deg<<<(E + 255) / 256, 256>>>(dst, E);
    k_dinv<<<(n + 255) / 256, 256>>>(n);

    // K3: GEMM + dinv scale (also seeds g_agg with the self-loop term)
    dim3 gblk(16, 16);
    dim3 ggrd(HIDDEN / BN, (n + BM - 1) / BM);
    k_gemm1<<<ggrd, gblk>>>(x, W1, n);

    // K4: edge scatter (64 float4 chunks per edge)
    long long total = (long long)E * 64;
    int sblocks = (int)((total + 255) / 256);
    k_scatter<<<sblocks, 256>>>(src, dst, E);

    // K5: finalize (1 warp per node)
    int fblocks = (n * 32 + 255) / 256;
    k_final<<<fblocks, 256>>>(b1, W2, b2, out, n);
}

// round 2
// speedup vs baseline: 1.1197x; 1.1197x over previous
#include <cuda_runtime.h>
#include <math.h>

#define N_NODES 100000
#define N_EDGES 1600000
#define IN_DIM 768
#define HIDDEN 256
#define N_CLASSES 3

typedef unsigned long long u64;

// ---- device scratch (static; no allocation allowed) ----
__device__ float g_deg[N_NODES];
__device__ float g_dinv[N_NODES];
__device__ float g_h[(size_t)N_NODES * HIDDEN];    // h' = dinv[i] * (x@W1)[i]
__device__ float g_agg[(size_t)N_NODES * HIDDEN];  // running sum, init = h' (self loop)

// ---- packed f32x2 helpers (sm_103a; ptxas won't emit FFMA2 from C++) ----
__device__ __forceinline__ u64 bcast2(float v) {
    u64 r;
    asm("mov.b64 %0, {%1, %1};" : "=l"(r) : "f"(v));
    return r;
}
__device__ __forceinline__ u64 fma2(u64 a, u64 b, u64 c) {
    u64 d;
    asm("fma.rn.f32x2 %0, %1, %2, %3;" : "=l"(d) : "l"(a), "l"(b), "l"(c));
    return d;
}
__device__ __forceinline__ float2 unpack2(u64 v) {
    float2 f;
    asm("mov.b64 {%0, %1}, %2;" : "=f"(f.x), "=f"(f.y) : "l"(v));
    return f;
}

// ---------------------------------------------------------------------------
// K0: init degrees to 1.0 (self-loop included)
// ---------------------------------------------------------------------------
__global__ void k_init_deg(int n) {
    int i = blockIdx.x * blockDim.x + threadIdx.x;
    if (i < n) g_deg[i] = 1.0f;
}

// ---------------------------------------------------------------------------
// K1: histogram destination degrees
// ---------------------------------------------------------------------------
__global__ void k_deg(const int* __restrict__ dst, int E) {
    int i = blockIdx.x * blockDim.x + threadIdx.x;
    if (i < E) atomicAdd(&g_deg[dst[i]], 1.0f);
}

// ---------------------------------------------------------------------------
// K2: dinv = rsqrt(deg)   (deg >= 1 always)
// ---------------------------------------------------------------------------
__global__ void k_dinv(int n) {
    int i = blockIdx.x * blockDim.x + threadIdx.x;
    if (i < n) g_dinv[i] = rsqrtf(g_deg[i]);
}

// ---------------------------------------------------------------------------
// K3: fp32 GEMM  h' = dinv[row] * (x @ W1), written to g_h AND g_agg
//   BM=128, BN=128, BK=8, 256 threads, 8x8 microtile via packed fma.rn.f32x2,
//   double-buffered smem.
// ---------------------------------------------------------------------------
#define BM 128
#define BN 128
#define BK 8
#define KT (IN_DIM / BK)   // 96 k-tiles

__global__ __launch_bounds__(256, 2) void k_gemm1(const float* __restrict__ x,
                                                  const float* __restrict__ W1,
                                                  int n) {
    __shared__ float As[2][BK][BM];   // A transposed: As[buf][k][m]  (4KB each)
    __shared__ float Bs[2][BK][BN];

    const int tid = threadIdx.x;      // 0..255
    const int tx = tid & 15;          // col group 0..15
    const int ty = tid >> 4;          // row group 0..15
    const int row0 = blockIdx.y * BM;
    const int col0 = blockIdx.x * BN;

    // A-tile load mapping: one float4 per thread (128 rows x 8 k)
    const int a_m = tid >> 1;         // 0..127
    const int a_k4 = (tid & 1) * 4;   // 0 or 4
    // B-tile load mapping: one float4 per thread (8 k x 128 n)
    const int b_k = tid >> 5;         // 0..7
    const int b_n4 = (tid & 31) * 4;  // 0..124

    const int a_row = row0 + a_m;
    const bool a_ok = (a_row < n);
    const float* a_ptr = x + (size_t)a_row * IN_DIM + a_k4;
    const float* b_ptr = W1 + (size_t)b_k * HIDDEN + col0 + b_n4;

    u64 acc[4][8];                    // 4 row-pairs x 8 cols, packed f32x2
#pragma unroll
    for (int i = 0; i < 4; i++)
#pragma unroll
        for (int j = 0; j < 8; j++) acc[i][j] = 0ull;

    // preload tile 0
    float4 va = make_float4(0.f, 0.f, 0.f, 0.f);
    if (a_ok) va = *reinterpret_cast<const float4*>(a_ptr);
    float4 vb = *reinterpret_cast<const float4*>(b_ptr);
    As[0][a_k4 + 0][a_m] = va.x;
    As[0][a_k4 + 1][a_m] = va.y;
    As[0][a_k4 + 2][a_m] = va.z;
    As[0][a_k4 + 3][a_m] = va.w;
    *reinterpret_cast<float4*>(&Bs[0][b_k][b_n4]) = vb;
    __syncthreads();

    int buf = 0;
    for (int t = 0; t < KT; t++) {
        // prefetch next tile into registers
        if (t + 1 < KT) {
            va = make_float4(0.f, 0.f, 0.f, 0.f);
            if (a_ok) va = *reinterpret_cast<const float4*>(a_ptr + (t + 1) * BK);
            vb = *reinterpret_cast<const float4*>(b_ptr + (size_t)(t + 1) * BK * HIDDEN);
        }

        // compute current tile
#pragma unroll
        for (int k = 0; k < BK; k++) {
            const u64* ap = reinterpret_cast<const u64*>(&As[buf][k][ty * 8]);
            u64 aa0 = ap[0], aa1 = ap[1], aa2 = ap[2], aa3 = ap[3];
            float4 bl = *reinterpret_cast<const float4*>(&Bs[buf][k][tx * 8]);
            float4 bh = *reinterpret_cast<const float4*>(&Bs[buf][k][tx * 8 + 4]);
            u64 bb0 = bcast2(bl.x), bb1 = bcast2(bl.y), bb2 = bcast2(bl.z), bb3 = bcast2(bl.w);
            u64 bb4 = bcast2(bh.x), bb5 = bcast2(bh.y), bb6 = bcast2(bh.z), bb7 = bcast2(bh.w);

            acc[0][0] = fma2(aa0, bb0, acc[0][0]);
            acc[0][1] = fma2(aa0, bb1, acc[0][1]);
            acc[0][2] = fma2(aa0, bb2, acc[0][2]);
            acc[0][3] = fma2(aa0, bb3, acc[0][3]);
            acc[0][4] = fma2(aa0, bb4, acc[0][4]);
            acc[0][5] = fma2(aa0, bb5, acc[0][5]);
            acc[0][6] = fma2(aa0, bb6, acc[0][6]);
            acc[0][7] = fma2(aa0, bb7, acc[0][7]);
            acc[1][0] = fma2(aa1, bb0, acc[1][0]);
            acc[1][1] = fma2(aa1, bb1, acc[1][1]);
            acc[1][2] = fma2(aa1, bb2, acc[1][2]);
            acc[1][3] = fma2(aa1, bb3, acc[1][3]);
            acc[1][4] = fma2(aa1, bb4, acc[1][4]);
            acc[1][5] = fma2(aa1, bb5, acc[1][5]);
            acc[1][6] = fma2(aa1, bb6, acc[1][6]);
            acc[1][7] = fma2(aa1, bb7, acc[1][7]);
            acc[2][0] = fma2(aa2, bb0, acc[2][0]);
            acc[2][1] = fma2(aa2, bb1, acc[2][1]);
            acc[2][2] = fma2(aa2, bb2, acc[2][2]);
            acc[2][3] = fma2(aa2, bb3, acc[2][3]);
            acc[2][4] = fma2(aa2, bb4, acc[2][4]);
            acc[2][5] = fma2(aa2, bb5, acc[2][5]);
            acc[2][6] = fma2(aa2, bb6, acc[2][6]);
            acc[2][7] = fma2(aa2, bb7, acc[2][7]);
            acc[3][0] = fma2(aa3, bb0, acc[3][0]);
            acc[3][1] = fma2(aa3, bb1, acc[3][1]);
            acc[3][2] = fma2(aa3, bb2, acc[3][2]);
            acc[3][3] = fma2(aa3, bb3, acc[3][3]);
            acc[3][4] = fma2(aa3, bb4, acc[3][4]);
            acc[3][5] = fma2(aa3, bb5, acc[3][5]);
            acc[3][6] = fma2(aa3, bb6, acc[3][6]);
            acc[3][7] = fma2(aa3, bb7, acc[3][7]);
        }

        // stage next tile into the other buffer
        if (t + 1 < KT) {
            int nb = buf ^ 1;
            As[nb][a_k4 + 0][a_m] = va.x;
            As[nb][a_k4 + 1][a_m] = va.y;
            As[nb][a_k4 + 2][a_m] = va.z;
            As[nb][a_k4 + 3][a_m] = va.w;
            *reinterpret_cast<float4*>(&Bs[nb][b_k][b_n4]) = vb;
        }
        __syncthreads();
        buf ^= 1;
    }

    // epilogue: unpack, scale by dinv, dual-store (g_h = h', g_agg = self-loop seed)
#pragma unroll
    for (int i = 0; i < 4; i++) {
        float2 p[8];
#pragma unroll
        for (int j = 0; j < 8; j++) p[j] = unpack2(acc[i][j]);
#pragma unroll
        for (int half = 0; half < 2; half++) {
            int r = row0 + ty * 8 + 2 * i + half;
            if (r >= n) continue;
            float s = g_dinv[r];
            float4 v0, v1;
            v0.x = (half ? p[0].y : p[0].x) * s;
            v0.y = (half ? p[1].y : p[1].x) * s;
            v0.z = (half ? p[2].y : p[2].x) * s;
            v0.w = (half ? p[3].y : p[3].x) * s;
            v1.x = (half ? p[4].y : p[4].x) * s;
            v1.y = (half ? p[5].y : p[5].x) * s;
            v1.z = (half ? p[6].y : p[6].x) * s;
            v1.w = (half ? p[7].y : p[7].x) * s;
            size_t off = (size_t)r * HIDDEN + col0 + tx * 8;
            *reinterpret_cast<float4*>(g_h + off) = v0;
            *reinterpret_cast<float4*>(g_h + off + 4) = v1;
            *reinterpret_cast<float4*>(g_agg + off) = v0;
            *reinterpret_cast<float4*>(g_agg + off + 4) = v1;
        }
    }
}

// ---------------------------------------------------------------------------
// K4: edge scatter: g_agg[dst] += g_h[src]   (vector f32x4 reductions)
// ---------------------------------------------------------------------------
__global__ __launch_bounds__(256) void k_scatter(const int* __restrict__ src,
                                                 const int* __restrict__ dst,
                                                 int E) {
    long long t = (long long)blockIdx.x * 256 + threadIdx.x;
    int e = (int)(t >> 6);
    int c = (int)(t & 63);
    if (e >= E) return;
    int s = __ldg(&src[e]);
    int d = __ldg(&dst[e]);
    float4 v = *reinterpret_cast<const float4*>(g_h + (size_t)s * HIDDEN + c * 4);
    float* ap = g_agg + (size_t)d * HIDDEN + c * 4;
    asm volatile("red.global.add.v4.f32 [%0], {%1, %2, %3, %4};"
                 :: "l"(ap), "f"(v.x), "f"(v.y), "f"(v.z), "f"(v.w)
                 : "memory");
}

// ---------------------------------------------------------------------------
// K5: finalize: logits = relu(dinv[i]*agg[i] + b1) @ W2 + b2 -> log_softmax
// ---------------------------------------------------------------------------
__global__ __launch_bounds__(256) void k_final(const float* __restrict__ b1,
                                               const float* __restrict__ W2,
                                               const float* __restrict__ b2,
                                               float* __restrict__ out,
                                               int n) {
    __shared__ float sW2[HIDDEN * N_CLASSES];
    __shared__ float sb1[HIDDEN];
    for (int i = threadIdx.x; i < HIDDEN * N_CLASSES; i += blockDim.x) sW2[i] = W2[i];
    for (int i = threadIdx.x; i < HIDDEN; i += blockDim.x) sb1[i] = b1[i];
    __syncthreads();

    int gwarp = (blockIdx.x * blockDim.x + threadIdx.x) >> 5;
    int lane = threadIdx.x & 31;
    if (gwarp >= n) return;

    float di = g_dinv[gwarp];
    const float4* ap = reinterpret_cast<const float4*>(g_agg + (size_t)gwarp * HIDDEN);

    float acc0 = 0.f, acc1 = 0.f, acc2 = 0.f;
#pragma unroll
    for (int cc = 0; cc < 2; cc++) {
        int c = lane + cc * 32;           // float4 index 0..63
        float4 v = ap[c];
        int base = c * 4;
        float h0 = fmaxf(fmaf(di, v.x, sb1[base + 0]), 0.f);
        float h1 = fmaxf(fmaf(di, v.y, sb1[base + 1]), 0.f);
        float h2 = fmaxf(fmaf(di, v.z, sb1[base + 2]), 0.f);
        float h3 = fmaxf(fmaf(di, v.w, sb1[base + 3]), 0.f);
        acc0 += h0 * sW2[(base + 0) * 3 + 0] + h1 * sW2[(base + 1) * 3 + 0]
              + h2 * sW2[(base + 2) * 3 + 0] + h3 * sW2[(base + 3) * 3 + 0];
        acc1 += h0 * sW2[(base + 0) * 3 + 1] + h1 * sW2[(base + 1) * 3 + 1]
              + h2 * sW2[(base + 2) * 3 + 1] + h3 * sW2[(base + 3) * 3 + 1];
        acc2 += h0 * sW2[(base + 0) * 3 + 2] + h1 * sW2[(base + 1) * 3 + 2]
              + h2 * sW2[(base + 2) * 3 + 2] + h3 * sW2[(base + 3) * 3 + 2];
    }
#pragma unroll
    for (int o = 16; o > 0; o >>= 1) {
        acc0 += __shfl_down_sync(0xFFFFFFFFu, acc0, o);
        acc1 += __shfl_down_sync(0xFFFFFFFFu, acc1, o);
        acc2 += __shfl_down_sync(0xFFFFFFFFu, acc2, o);
    }
    if (lane == 0) {
        float l0 = acc0 + b2[0];
        float l1 = acc1 + b2[1];
        float l2 = acc2 + b2[2];
        float m = fmaxf(l0, fmaxf(l1, l2));
        float se = expf(l0 - m) + expf(l1 - m) + expf(l2 - m);
        float lse = m + logf(se);
        out[(size_t)gwarp * 3 + 0] = l0 - lse;
        out[(size_t)gwarp * 3 + 1] = l1 - lse;
        out[(size_t)gwarp * 3 + 2] = l2 - lse;
    }
}

// ---------------------------------------------------------------------------
extern "C" void kernel_launch(void* const* d_in, const int* in_sizes, int n_in,
                              void* d_out, int out_size) {
    const float* x  = (const float*)d_in[0];
    const int*   ei = (const int*)d_in[1];
    const float* W1 = (const float*)d_in[2];
    const float* b1 = (const float*)d_in[3];
    const float* W2 = (const float*)d_in[4];
    const float* b2 = (const float*)d_in[5];
    float* out = (float*)d_out;

    int n = in_sizes[0] / IN_DIM;
    int E = in_sizes[1] / 2;
    const int* src = ei;
    const int* dst = ei + E;

    // K0/K1/K2: degree normalization
    k_init_deg<<<(n + 255) / 256, 256>>>(n);
    k_deg<<<(E + 255) / 256, 256>>>(dst, E);
    k_dinv<<<(n + 255) / 256, 256>>>(n);

    // K3: GEMM + dinv scale (also seeds g_agg with the self-loop term)
    dim3 ggrd(HIDDEN / BN, (n + BM - 1) / BM);
    k_gemm1<<<ggrd, 256>>>(x, W1, n);

    // K4: edge scatter (64 float4 chunks per edge)
    long long total = (long long)E * 64;
    int sblocks = (int)((total + 255) / 256);
    k_scatter<<<sblocks, 256>>>(src, dst, E);

    // K5: finalize (1 warp per node)
    int fblocks = (n * 32 + 255) / 256;
    k_final<<<fblocks, 256>>>(b1, W2, b2, out, n);
}

// round 4
// speedup vs baseline: 1.4596x; 1.3036x over previous
#include <cuda_runtime.h>
#include <cuda_bf16.h>
#include <math.h>
#include <stdint.h>

#define N_NODES 100000
#define N_EDGES 1600000
#define IN_DIM 768
#define HIDDEN 256
#define N_CLASSES 3

// ---- device scratch (static; no allocation allowed) ----
__device__ float g_deg[N_NODES];
__device__ float g_dinv[N_NODES];
__device__ float g_h[(size_t)N_NODES * HIDDEN];    // h' = dinv[i] * (x@W1)[i]
__device__ float g_agg[(size_t)N_NODES * HIDDEN];  // running sum, init = h' (self loop)
__device__ __nv_bfloat16 g_w1t_hi[(size_t)HIDDEN * IN_DIM];  // W1^T split-hi [256][768]
__device__ __nv_bfloat16 g_w1t_lo[(size_t)HIDDEN * IN_DIM];  // W1^T split-lo

// ---------------------------------------------------------------------------
// K0/K1/K2: degree normalization
// ---------------------------------------------------------------------------
__global__ void k_init_deg(int n) {
    int i = blockIdx.x * blockDim.x + threadIdx.x;
    if (i < n) g_deg[i] = 1.0f;
}
__global__ void k_deg(const int* __restrict__ dst, int E) {
    int i = blockIdx.x * blockDim.x + threadIdx.x;
    if (i < E) atomicAdd(&g_deg[dst[i]], 1.0f);
}
__global__ void k_dinv(int n) {
    int i = blockIdx.x * blockDim.x + threadIdx.x;
    if (i < n) g_dinv[i] = rsqrtf(g_deg[i]);
}

// ---------------------------------------------------------------------------
// K-prep: transpose + bf16-split W1 [768,256] -> W1t_hi/lo [256,768]
// ---------------------------------------------------------------------------
__global__ void k_prep_w1(const float* __restrict__ W1) {
    int idx = blockIdx.x * blockDim.x + threadIdx.x;
    if (idx >= IN_DIM * HIDDEN) return;
    int k = idx / HIDDEN;
    int nn = idx % HIDDEN;
    float w = W1[idx];
    __nv_bfloat16 hi = __float2bfloat16(w);
    __nv_bfloat16 lo = __float2bfloat16(w - __bfloat162float(hi));
    g_w1t_hi[(size_t)nn * IN_DIM + k] = hi;
    g_w1t_lo[(size_t)nn * IN_DIM + k] = lo;
}

// ---------------------------------------------------------------------------
// K3: HMMA GEMM  h' = dinv[row] * (x @ W1)  via 2-way bf16 split + mma.sync
//   CTA 256 thr, tile 128x128, warp tile 64x32 (m16n8k16), K chunks of 32
// ---------------------------------------------------------------------------
#define APAD 40   // smem row stride in halves (conflict-free frag loads)

__device__ __forceinline__ void mma_bf16(float* d, const uint32_t* a, const uint32_t* b) {
    asm volatile(
        "mma.sync.aligned.m16n8k16.row.col.f32.bf16.bf16.f32 "
        "{%0,%1,%2,%3}, {%4,%5,%6,%7}, {%8,%9}, {%0,%1,%2,%3};"
        : "+f"(d[0]), "+f"(d[1]), "+f"(d[2]), "+f"(d[3])
        : "r"(a[0]), "r"(a[1]), "r"(a[2]), "r"(a[3]), "r"(b[0]), "r"(b[1]));
}
__device__ __forceinline__ uint32_t pack_bf2(__nv_bfloat16 a, __nv_bfloat16 b) {
    return ((uint32_t)__bfloat16_as_ushort(b) << 16) | __bfloat16_as_ushort(a);
}

__global__ __launch_bounds__(256, 2) void k_gemm_hmma(const float* __restrict__ x, int n) {
    __shared__ __nv_bfloat16 Ahi[128][APAD];
    __shared__ __nv_bfloat16 Alo[128][APAD];
    __shared__ __nv_bfloat16 Bhi[128][APAD];
    __shared__ __nv_bfloat16 Blo[128][APAD];

    const int tid = threadIdx.x;
    const int wid = tid >> 5;
    const int lane = tid & 31;
    const int wm = wid >> 2;          // 0..1  (x64 rows)
    const int wn = wid & 3;           // 0..3  (x32 cols)
    const int gID = lane >> 2;        // 0..7
    const int tig = lane & 3;         // 0..3
    const int row0 = blockIdx.y * 128;
    const int col0 = blockIdx.x * 128;

    float acc[4][4][4];
#pragma unroll
    for (int i = 0; i < 4; i++)
#pragma unroll
        for (int j = 0; j < 4; j++)
#pragma unroll
            for (int q = 0; q < 4; q++) acc[i][j][q] = 0.0f;

    // global load mapping: 2 threads per row, 16 elements each
    const int arow = tid >> 1;
    const int acol = (tid & 1) * 16;
    const int grow = row0 + arow;
    const bool a_ok = (grow < n);
    const float* aptr = x + (size_t)(a_ok ? grow : 0) * IN_DIM + acol;
    const __nv_bfloat16* bhptr = g_w1t_hi + (size_t)(col0 + arow) * IN_DIM + acol;
    const __nv_bfloat16* blptr = g_w1t_lo + (size_t)(col0 + arow) * IN_DIM + acol;

    for (int k0 = 0; k0 < IN_DIM; k0 += 32) {
        // ---- load + split A chunk (128 x 32 fp32) ----
        float f[16];
#pragma unroll
        for (int j = 0; j < 4; j++) {
            float4 v = a_ok ? *reinterpret_cast<const float4*>(aptr + k0 + j * 4)
                            : make_float4(0.f, 0.f, 0.f, 0.f);
            f[j * 4 + 0] = v.x; f[j * 4 + 1] = v.y; f[j * 4 + 2] = v.z; f[j * 4 + 3] = v.w;
        }
        uint32_t hiw[8], low[8];
#pragma unroll
        for (int j = 0; j < 8; j++) {
            __nv_bfloat16 h0 = __float2bfloat16(f[j * 2 + 0]);
            __nv_bfloat16 h1 = __float2bfloat16(f[j * 2 + 1]);
            __nv_bfloat16 l0 = __float2bfloat16(f[j * 2 + 0] - __bfloat162float(h0));
            __nv_bfloat16 l1 = __float2bfloat16(f[j * 2 + 1] - __bfloat162float(h1));
            hiw[j] = pack_bf2(h0, h1);
            low[j] = pack_bf2(l0, l1);
        }
        *reinterpret_cast<uint4*>(&Ahi[arow][acol])     = make_uint4(hiw[0], hiw[1], hiw[2], hiw[3]);
        *reinterpret_cast<uint4*>(&Ahi[arow][acol + 8]) = make_uint4(hiw[4], hiw[5], hiw[6], hiw[7]);
        *reinterpret_cast<uint4*>(&Alo[arow][acol])     = make_uint4(low[0], low[1], low[2], low[3]);
        *reinterpret_cast<uint4*>(&Alo[arow][acol + 8]) = make_uint4(low[4], low[5], low[6], low[7]);

        // ---- load B chunk (128 x 32 bf16, hi & lo) ----
        {
            uint4 v0 = *reinterpret_cast<const uint4*>(bhptr + k0);
            uint4 v1 = *reinterpret_cast<const uint4*>(bhptr + k0 + 8);
            *reinterpret_cast<uint4*>(&Bhi[arow][acol])     = v0;
            *reinterpret_cast<uint4*>(&Bhi[arow][acol + 8]) = v1;
            uint4 w0 = *reinterpret_cast<const uint4*>(blptr + k0);
            uint4 w1 = *reinterpret_cast<const uint4*>(blptr + k0 + 8);
            *reinterpret_cast<uint4*>(&Blo[arow][acol])     = w0;
            *reinterpret_cast<uint4*>(&Blo[arow][acol + 8]) = w1;
        }
        __syncthreads();

        // ---- compute: 2 k-steps of 16 ----
#pragma unroll
        for (int kk = 0; kk < 32; kk += 16) {
            uint32_t bh[4][2], bl[4][2];
#pragma unroll
            for (int nf = 0; nf < 4; nf++) {
                int bn = wn * 32 + nf * 8 + gID;
                bh[nf][0] = *reinterpret_cast<const uint32_t*>(&Bhi[bn][kk + 2 * tig]);
                bh[nf][1] = *reinterpret_cast<const uint32_t*>(&Bhi[bn][kk + 2 * tig + 8]);
                bl[nf][0] = *reinterpret_cast<const uint32_t*>(&Blo[bn][kk + 2 * tig]);
                bl[nf][1] = *reinterpret_cast<const uint32_t*>(&Blo[bn][kk + 2 * tig + 8]);
            }
#pragma unroll
            for (int mf = 0; mf < 4; mf++) {
                int am = wm * 64 + mf * 16 + gID;
                uint32_t ah[4], al[4];
                ah[0] = *reinterpret_cast<const uint32_t*>(&Ahi[am][kk + 2 * tig]);
                ah[1] = *reinterpret_cast<const uint32_t*>(&Ahi[am + 8][kk + 2 * tig]);
                ah[2] = *reinterpret_cast<const uint32_t*>(&Ahi[am][kk + 2 * tig + 8]);
                ah[3] = *reinterpret_cast<const uint32_t*>(&Ahi[am + 8][kk + 2 * tig + 8]);
                al[0] = *reinterpret_cast<const uint32_t*>(&Alo[am][kk + 2 * tig]);
                al[1] = *reinterpret_cast<const uint32_t*>(&Alo[am + 8][kk + 2 * tig]);
                al[2] = *reinterpret_cast<const uint32_t*>(&Alo[am][kk + 2 * tig + 8]);
                al[3] = *reinterpret_cast<const uint32_t*>(&Alo[am + 8][kk + 2 * tig + 8]);
#pragma unroll
                for (int nf = 0; nf < 4; nf++) {
                    mma_bf16(acc[mf][nf], ah, bh[nf]);
                    mma_bf16(acc[mf][nf], ah, bl[nf]);
                    mma_bf16(acc[mf][nf], al, bh[nf]);
                }
            }
        }
        __syncthreads();
    }

    // ---- epilogue: scale by dinv, dual store ----
#pragma unroll
    for (int mf = 0; mf < 4; mf++) {
        int r0 = row0 + wm * 64 + mf * 16 + gID;
        int r1 = r0 + 8;
        float s0 = (r0 < n) ? g_dinv[r0] : 0.f;
        float s1 = (r1 < n) ? g_dinv[r1] : 0.f;
#pragma unroll
        for (int nf = 0; nf < 4; nf++) {
            int c = col0 + wn * 32 + nf * 8 + 2 * tig;
            if (r0 < n) {
                float2 v = make_float2(acc[mf][nf][0] * s0, acc[mf][nf][1] * s0);
                *reinterpret_cast<float2*>(g_h + (size_t)r0 * HIDDEN + c) = v;
                *reinterpret_cast<float2*>(g_agg + (size_t)r0 * HIDDEN + c) = v;
            }
            if (r1 < n) {
                float2 v = make_float2(acc[mf][nf][2] * s1, acc[mf][nf][3] * s1);
                *reinterpret_cast<float2*>(g_h + (size_t)r1 * HIDDEN + c) = v;
                *reinterpret_cast<float2*>(g_agg + (size_t)r1 * HIDDEN + c) = v;
            }
        }
    }
}

// ---------------------------------------------------------------------------
// K4: edge scatter: g_agg[dst] += g_h[src]   (vector f32x4 reductions)
// ---------------------------------------------------------------------------
__global__ __launch_bounds__(256) void k_scatter(const int* __restrict__ src,
                                                 const int* __restrict__ dst,
                                                 int E) {
    long long t = (long long)blockIdx.x * 256 + threadIdx.x;
    int e = (int)(t >> 6);
    int c = (int)(t & 63);
    if (e >= E) return;
    int s = __ldg(&src[e]);
    int d = __ldg(&dst[e]);
    float4 v = *reinterpret_cast<const float4*>(g_h + (size_t)s * HIDDEN + c * 4);
    float* ap = g_agg + (size_t)d * HIDDEN + c * 4;
    asm volatile("red.global.add.v4.f32 [%0], {%1, %2, %3, %4};"
                 :: "l"(ap), "f"(v.x), "f"(v.y), "f"(v.z), "f"(v.w)
                 : "memory");
}

// ---------------------------------------------------------------------------
// K5: finalize: logits = relu(dinv[i]*agg[i] + b1) @ W2 + b2 -> log_softmax
// ---------------------------------------------------------------------------
__global__ __launch_bounds__(256) void k_final(const float* __restrict__ b1,
                                               const float* __restrict__ W2,
                                               const float* __restrict__ b2,
                                               float* __restrict__ out,
                                               int n) {
    __shared__ float sW2[HIDDEN * N_CLASSES];
    __shared__ float sb1[HIDDEN];
    for (int i = threadIdx.x; i < HIDDEN * N_CLASSES; i += blockDim.x) sW2[i] = W2[i];
    for (int i = threadIdx.x; i < HIDDEN; i += blockDim.x) sb1[i] = b1[i];
    __syncthreads();

    int gwarp = (blockIdx.x * blockDim.x + threadIdx.x) >> 5;
    int lane = threadIdx.x & 31;
    if (gwarp >= n) return;

    float di = g_dinv[gwarp];
    const float4* ap = reinterpret_cast<const float4*>(g_agg + (size_t)gwarp * HIDDEN);

    float acc0 = 0.f, acc1 = 0.f, acc2 = 0.f;
#pragma unroll
    for (int cc = 0; cc < 2; cc++) {
        int c = lane + cc * 32;
        float4 v = ap[c];
        int base = c * 4;
        float h0 = fmaxf(fmaf(di, v.x, sb1[base + 0]), 0.f);
        float h1 = fmaxf(fmaf(di, v.y, sb1[base + 1]), 0.f);
        float h2 = fmaxf(fmaf(di, v.z, sb1[base + 2]), 0.f);
        float h3 = fmaxf(fmaf(di, v.w, sb1[base + 3]), 0.f);
        acc0 += h0 * sW2[(base + 0) * 3 + 0] + h1 * sW2[(base + 1) * 3 + 0]
              + h2 * sW2[(base + 2) * 3 + 0] + h3 * sW2[(base + 3) * 3 + 0];
        acc1 += h0 * sW2[(base + 0) * 3 + 1] + h1 * sW2[(base + 1) * 3 + 1]
              + h2 * sW2[(base + 2) * 3 + 1] + h3 * sW2[(base + 3) * 3 + 1];
        acc2 += h0 * sW2[(base + 0) * 3 + 2] + h1 * sW2[(base + 1) * 3 + 2]
              + h2 * sW2[(base + 2) * 3 + 2] + h3 * sW2[(base + 3) * 3 + 2];
    }
#pragma unroll
    for (int o = 16; o > 0; o >>= 1) {
        acc0 += __shfl_down_sync(0xFFFFFFFFu, acc0, o);
        acc1 += __shfl_down_sync(0xFFFFFFFFu, acc1, o);
        acc2 += __shfl_down_sync(0xFFFFFFFFu, acc2, o);
    }
    if (lane == 0) {
        float l0 = acc0 + b2[0];
        float l1 = acc1 + b2[1];
        float l2 = acc2 + b2[2];
        float m = fmaxf(l0, fmaxf(l1, l2));
        float se = expf(l0 - m) + expf(l1 - m) + expf(l2 - m);
        float lse = m + logf(se);
        out[(size_t)gwarp * 3 + 0] = l0 - lse;
        out[(size_t)gwarp * 3 + 1] = l1 - lse;
        out[(size_t)gwarp * 3 + 2] = l2 - lse;
    }
}

// ---------------------------------------------------------------------------
extern "C" void kernel_launch(void* const* d_in, const int* in_sizes, int n_in,
                              void* d_out, int out_size) {
    const float* x  = (const float*)d_in[0];
    const int*   ei = (const int*)d_in[1];
    const float* W1 = (const float*)d_in[2];
    const float* b1 = (const float*)d_in[3];
    const float* W2 = (const float*)d_in[4];
    const float* b2 = (const float*)d_in[5];
    float* out = (float*)d_out;

    int n = in_sizes[0] / IN_DIM;
    int E = in_sizes[1] / 2;
    const int* src = ei;
    const int* dst = ei + E;

    // degree normalization
    k_init_deg<<<(n + 255) / 256, 256>>>(n);
    k_deg<<<(E + 255) / 256, 256>>>(dst, E);
    k_dinv<<<(n + 255) / 256, 256>>>(n);

    // W1 split/transpose prep
    k_prep_w1<<<(IN_DIM * HIDDEN + 255) / 256, 256>>>(W1);

    // HMMA GEMM + dinv scale (also seeds g_agg with self-loop term)
    dim3 ggrd(HIDDEN / 128, (n + 127) / 128);
    k_gemm_hmma<<<ggrd, 256>>>(x, n);

    // edge scatter
    long long total = (long long)E * 64;
    int sblocks = (int)((total + 255) / 256);
    k_scatter<<<sblocks, 256>>>(src, dst, E);

    // finalize
    int fblocks = (n * 32 + 255) / 256;
    k_final<<<fblocks, 256>>>(b1, W2, b2, out, n);
}

// round 5
// speedup vs baseline: 2.7895x; 1.9112x over previous
#include <cuda_runtime.h>
#include <cuda_bf16.h>
#include <math.h>
#include <stdint.h>

#define N_NODES 100000
#define N_EDGES 1600000
#define IN_DIM 768
#define HIDDEN 256
#define N_CLASSES 3

// ---- device scratch (static; no allocation allowed) ----
__device__ float g_dinv[N_NODES];
__device__ float g_h[(size_t)N_NODES * HIDDEN];    // h' = dinv[i] * (x@W1)[i]
__device__ int g_cnt[N_NODES];
__device__ int g_off[N_NODES + 1];
__device__ int g_cur[N_NODES];
__device__ int g_csr[N_EDGES];
__device__ __nv_bfloat16 g_w1t_hi[(size_t)HIDDEN * IN_DIM];  // W1^T split-hi [256][768]
__device__ __nv_bfloat16 g_w1t_lo[(size_t)HIDDEN * IN_DIM];  // W1^T split-lo

// ---------------------------------------------------------------------------
// helpers
// ---------------------------------------------------------------------------
__device__ __forceinline__ uint32_t smem_u32(const void* p) {
    uint32_t a;
    asm("{ .reg .u64 t; cvta.to.shared.u64 t, %1; cvt.u32.u64 %0, t; }" : "=r"(a) : "l"(p));
    return a;
}
__device__ __forceinline__ void mma_bf16(float* d, const uint32_t* a, const uint32_t* b) {
    asm volatile(
        "mma.sync.aligned.m16n8k16.row.col.f32.bf16.bf16.f32 "
        "{%0,%1,%2,%3}, {%4,%5,%6,%7}, {%8,%9}, {%0,%1,%2,%3};"
        : "+f"(d[0]), "+f"(d[1]), "+f"(d[2]), "+f"(d[3])
        : "r"(a[0]), "r"(a[1]), "r"(a[2]), "r"(a[3]), "r"(b[0]), "r"(b[1]));
}
__device__ __forceinline__ void ldmat_x4(uint32_t* r, uint32_t addr) {
    asm volatile("ldmatrix.sync.aligned.m8n8.x4.shared.b16 {%0,%1,%2,%3}, [%4];"
                 : "=r"(r[0]), "=r"(r[1]), "=r"(r[2]), "=r"(r[3]) : "r"(addr));
}
__device__ __forceinline__ uint32_t pack_bf2(__nv_bfloat16 a, __nv_bfloat16 b) {
    return ((uint32_t)__bfloat16_as_ushort(b) << 16) | __bfloat16_as_ushort(a);
}
#define CP_ASYNC16(dst, src) \
    asm volatile("cp.async.ca.shared.global [%0], [%1], 16;" :: "r"(dst), "l"(src))
#define CP_COMMIT() asm volatile("cp.async.commit_group;" ::: "memory")
#define CP_WAIT0()  asm volatile("cp.async.wait_group 0;" ::: "memory")

// ---------------------------------------------------------------------------
// degree / CSR build
// ---------------------------------------------------------------------------
__global__ void k_zero_cnt(int n) {
    int i = blockIdx.x * blockDim.x + threadIdx.x;
    if (i < n) g_cnt[i] = 0;
}
__global__ void k_cnt(const int* __restrict__ dst, int E) {
    int i = blockIdx.x * blockDim.x + threadIdx.x;
    if (i < E) atomicAdd(&g_cnt[dst[i]], 1);
}
// single-block exclusive prefix sum over g_cnt -> g_off (warp-scan based)
__global__ void k_scan(int n) {
    __shared__ int swarp[32];
    __shared__ int carry_s;
    const int t = threadIdx.x;
    const int lane = t & 31;
    const int wid = t >> 5;
    if (t == 0) { carry_s = 0; g_off[0] = 0; }
    __syncthreads();
    for (int base = 0; base < n; base += 1024) {
        int i = base + t;
        int v = (i < n) ? g_cnt[i] : 0;
        int x = v;
#pragma unroll
        for (int o = 1; o < 32; o <<= 1) {
            int u = __shfl_up_sync(0xFFFFFFFFu, x, o);
            if (lane >= o) x += u;
        }
        if (lane == 31) swarp[wid] = x;
        __syncthreads();
        if (wid == 0) {
            int y = swarp[lane];
#pragma unroll
            for (int o = 1; o < 32; o <<= 1) {
                int u = __shfl_up_sync(0xFFFFFFFFu, y, o);
                if (lane >= o) y += u;
            }
            swarp[lane] = y;
        }
        __syncthreads();
        int pre = (wid > 0) ? swarp[wid - 1] : 0;
        int incl = carry_s + pre + x;
        if (i < n) g_off[i + 1] = incl;
        int total = swarp[31];
        __syncthreads();
        if (t == 0) carry_s += total;
        __syncthreads();
    }
}
__global__ void k_dinv_cur(int n) {
    int i = blockIdx.x * blockDim.x + threadIdx.x;
    if (i < n) {
        g_dinv[i] = rsqrtf(1.0f + (float)g_cnt[i]);
        g_cur[i] = g_off[i];
    }
}
__global__ void k_fill(const int* __restrict__ src, const int* __restrict__ dst, int E) {
    int e = blockIdx.x * blockDim.x + threadIdx.x;
    if (e < E) {
        int d = dst[e];
        int pos = atomicAdd(&g_cur[d], 1);
        g_csr[pos] = src[e];
    }
}

// ---------------------------------------------------------------------------
// W1 prep: transpose + bf16 split
// ---------------------------------------------------------------------------
__global__ void k_prep_w1(const float* __restrict__ W1) {
    int idx = blockIdx.x * blockDim.x + threadIdx.x;
    if (idx >= IN_DIM * HIDDEN) return;
    int k = idx / HIDDEN;
    int nn = idx % HIDDEN;
    float w = W1[idx];
    __nv_bfloat16 hi = __float2bfloat16(w);
    __nv_bfloat16 lo = __float2bfloat16(w - __bfloat162float(hi));
    g_w1t_hi[(size_t)nn * IN_DIM + k] = hi;
    g_w1t_lo[(size_t)nn * IN_DIM + k] = lo;
}

// ---------------------------------------------------------------------------
// GEMM: h' = dinv[row] * (x @ W1), 2-way bf16 split, mma.sync + ldmatrix,
// double-buffered smem, cp.async for B, register prefetch for A.
// CTA 256 thr, tile 128x128, warp tile 64x32, K chunks of 32.
// ---------------------------------------------------------------------------
// smem layout per buffer (bytes): rows of 40 halves (80B stride)
#define AHI_OFF 0
#define ALO_OFF 10240
#define BHI_OFF 20480
#define BLO_OFF 30720
#define SMB 40960
#define GEMM_SMEM (2 * SMB)

extern __shared__ char smem_raw[];

__global__ __launch_bounds__(256, 2) void k_gemm_hmma(const float* __restrict__ x, int n) {
    const uint32_t sb = smem_u32(smem_raw);
    const int tid = threadIdx.x;
    const int wid = tid >> 5;
    const int lane = tid & 31;
    const int wm = wid >> 2;          // 0..1
    const int wn = wid & 3;           // 0..3
    const int gID = lane >> 2;
    const int tig = lane & 3;
    const int row0 = blockIdx.y * 128;
    const int col0 = blockIdx.x * 128;

    float acc[4][4][4];
#pragma unroll
    for (int i = 0; i < 4; i++)
#pragma unroll
        for (int j = 0; j < 4; j++)
#pragma unroll
            for (int q = 0; q < 4; q++) acc[i][j][q] = 0.0f;

    // staging mapping: 2 threads per row, 16 cols each
    const int arow = tid >> 1;
    const int acol = (tid & 1) * 16;
    const int grow = row0 + arow;
    const bool a_ok = (grow < n);
    const float* aptr = x + (size_t)(a_ok ? grow : 0) * IN_DIM + acol;
    const __nv_bfloat16* bhptr = g_w1t_hi + (size_t)(col0 + arow) * IN_DIM + acol;
    const __nv_bfloat16* blptr = g_w1t_lo + (size_t)(col0 + arow) * IN_DIM + acol;
    const uint32_t st_off = (uint32_t)(arow * 80 + acol * 2);   // byte offset in tile

    // fragment byte offsets
    const uint32_t a_frag = (uint32_t)((lane & 15) * 80 + ((lane & 16) ? 16 : 0));
    const uint32_t b_frag = (uint32_t)(((lane & 7) + ((lane & 16) ? 8 : 0)) * 80 + ((lane & 8) ? 16 : 0));

    // ---- prologue: stage chunk 0 into buffer 0 ----
    {
        float f[16];
#pragma unroll
        for (int j = 0; j < 4; j++) {
            float4 v = a_ok ? *reinterpret_cast<const float4*>(aptr + j * 4)
                            : make_float4(0.f, 0.f, 0.f, 0.f);
            f[j * 4 + 0] = v.x; f[j * 4 + 1] = v.y; f[j * 4 + 2] = v.z; f[j * 4 + 3] = v.w;
        }
        uint32_t hiw[8], low[8];
#pragma unroll
        for (int j = 0; j < 8; j++) {
            __nv_bfloat16 h0 = __float2bfloat16(f[j * 2 + 0]);
            __nv_bfloat16 h1 = __float2bfloat16(f[j * 2 + 1]);
            __nv_bfloat16 l0 = __float2bfloat16(f[j * 2 + 0] - __bfloat162float(h0));
            __nv_bfloat16 l1 = __float2bfloat16(f[j * 2 + 1] - __bfloat162float(h1));
            hiw[j] = pack_bf2(h0, h1);
            low[j] = pack_bf2(l0, l1);
        }
        char* sm = smem_raw;
        *reinterpret_cast<uint4*>(sm + AHI_OFF + st_off)      = make_uint4(hiw[0], hiw[1], hiw[2], hiw[3]);
        *reinterpret_cast<uint4*>(sm + AHI_OFF + st_off + 16) = make_uint4(hiw[4], hiw[5], hiw[6], hiw[7]);
        *reinterpret_cast<uint4*>(sm + ALO_OFF + st_off)      = make_uint4(low[0], low[1], low[2], low[3]);
        *reinterpret_cast<uint4*>(sm + ALO_OFF + st_off + 16) = make_uint4(low[4], low[5], low[6], low[7]);
        CP_ASYNC16(sb + BHI_OFF + st_off,      bhptr);
        CP_ASYNC16(sb + BHI_OFF + st_off + 16, bhptr + 8);
        CP_ASYNC16(sb + BLO_OFF + st_off,      blptr);
        CP_ASYNC16(sb + BLO_OFF + st_off + 16, blptr + 8);
        CP_COMMIT();
    }
    CP_WAIT0();
    __syncthreads();

    int buf = 0;
    for (int c = 0; c < IN_DIM / 32; c++) {
        const bool has_next = (c + 1 < IN_DIM / 32);
        float f[16];
        if (has_next) {
            const int k1 = (c + 1) * 32;
            const uint32_t nb = (uint32_t)((buf ^ 1) * SMB);
            CP_ASYNC16(sb + nb + BHI_OFF + st_off,      bhptr + k1);
            CP_ASYNC16(sb + nb + BHI_OFF + st_off + 16, bhptr + k1 + 8);
            CP_ASYNC16(sb + nb + BLO_OFF + st_off,      blptr + k1);
            CP_ASYNC16(sb + nb + BLO_OFF + st_off + 16, blptr + k1 + 8);
            CP_COMMIT();
#pragma unroll
            for (int j = 0; j < 4; j++) {
                float4 v = a_ok ? *reinterpret_cast<const float4*>(aptr + k1 + j * 4)
                                : make_float4(0.f, 0.f, 0.f, 0.f);
                f[j * 4 + 0] = v.x; f[j * 4 + 1] = v.y; f[j * 4 + 2] = v.z; f[j * 4 + 3] = v.w;
            }
        }

        // ---- compute current buffer: 2 k-steps of 16 ----
        const uint32_t bb = sb + (uint32_t)(buf * SMB);
#pragma unroll
        for (int kk2 = 0; kk2 < 2; kk2++) {
            const uint32_t kkb = kk2 * 32;   // 16 halves = 32 bytes
            uint32_t bh[4][2], bl[4][2];
            {
                uint32_t r[4];
                ldmat_x4(r, bb + BHI_OFF + (uint32_t)(wn * 32) * 80 + kkb + b_frag);
                bh[0][0] = r[0]; bh[0][1] = r[1]; bh[1][0] = r[2]; bh[1][1] = r[3];
                ldmat_x4(r, bb + BHI_OFF + (uint32_t)(wn * 32 + 16) * 80 + kkb + b_frag);
                bh[2][0] = r[0]; bh[2][1] = r[1]; bh[3][0] = r[2]; bh[3][1] = r[3];
                ldmat_x4(r, bb + BLO_OFF + (uint32_t)(wn * 32) * 80 + kkb + b_frag);
                bl[0][0] = r[0]; bl[0][1] = r[1]; bl[1][0] = r[2]; bl[1][1] = r[3];
                ldmat_x4(r, bb + BLO_OFF + (uint32_t)(wn * 32 + 16) * 80 + kkb + b_frag);
                bl[2][0] = r[0]; bl[2][1] = r[1]; bl[3][0] = r[2]; bl[3][1] = r[3];
            }
#pragma unroll
            for (int mf = 0; mf < 4; mf++) {
                uint32_t ah[4], al[4];
                const uint32_t arow_off = (uint32_t)(wm * 64 + mf * 16) * 80 + kkb;
                ldmat_x4(ah, bb + AHI_OFF + arow_off + a_frag);
                ldmat_x4(al, bb + ALO_OFF + arow_off + a_frag);
#pragma unroll
                for (int nf = 0; nf < 4; nf++) {
                    mma_bf16(acc[mf][nf], ah, bh[nf]);
                    mma_bf16(acc[mf][nf], ah, bl[nf]);
                    mma_bf16(acc[mf][nf], al, bh[nf]);
                }
            }
        }

        // ---- stage A into next buffer ----
        if (has_next) {
            uint32_t hiw[8], low[8];
#pragma unroll
            for (int j = 0; j < 8; j++) {
                __nv_bfloat16 h0 = __float2bfloat16(f[j * 2 + 0]);
                __nv_bfloat16 h1 = __float2bfloat16(f[j * 2 + 1]);
                __nv_bfloat16 l0 = __float2bfloat16(f[j * 2 + 0] - __bfloat162float(h0));
                __nv_bfloat16 l1 = __float2bfloat16(f[j * 2 + 1] - __bfloat162float(h1));
                hiw[j] = pack_bf2(h0, h1);
                low[j] = pack_bf2(l0, l1);
            }
            char* sm = smem_raw + (buf ^ 1) * SMB;
            *reinterpret_cast<uint4*>(sm + AHI_OFF + st_off)      = make_uint4(hiw[0], hiw[1], hiw[2], hiw[3]);
            *reinterpret_cast<uint4*>(sm + AHI_OFF + st_off + 16) = make_uint4(hiw[4], hiw[5], hiw[6], hiw[7]);
            *reinterpret_cast<uint4*>(sm + ALO_OFF + st_off)      = make_uint4(low[0], low[1], low[2], low[3]);
            *reinterpret_cast<uint4*>(sm + ALO_OFF + st_off + 16) = make_uint4(low[4], low[5], low[6], low[7]);
        }
        CP_WAIT0();
        __syncthreads();
        buf ^= 1;
    }

    // ---- epilogue: scale by dinv, store g_h only ----
#pragma unroll
    for (int mf = 0; mf < 4; mf++) {
        int r0 = row0 + wm * 64 + mf * 16 + gID;
        int r1 = r0 + 8;
        float s0 = (r0 < n) ? g_dinv[r0] : 0.f;
        float s1 = (r1 < n) ? g_dinv[r1] : 0.f;
#pragma unroll
        for (int nf = 0; nf < 4; nf++) {
            int cc = col0 + wn * 32 + nf * 8 + 2 * tig;
            if (r0 < n)
                *reinterpret_cast<float2*>(g_h + (size_t)r0 * HIDDEN + cc) =
                    make_float2(acc[mf][nf][0] * s0, acc[mf][nf][1] * s0);
            if (r1 < n)
                *reinterpret_cast<float2*>(g_h + (size_t)r1 * HIDDEN + cc) =
                    make_float2(acc[mf][nf][2] * s1, acc[mf][nf][3] * s1);
        }
    }
}

// ---------------------------------------------------------------------------
// fused aggregate + finalize: warp per node
//   agg = h'[r] + sum_{s in N(r)} h'[s];  out = log_softmax(relu(dinv*agg+b1)@W2+b2)
// ---------------------------------------------------------------------------
__global__ __launch_bounds__(256) void k_aggfinal(const float* __restrict__ b1,
                                                  const float* __restrict__ W2,
                                                  const float* __restrict__ b2,
                                                  float* __restrict__ out,
                                                  int n) {
    __shared__ float sW2[HIDDEN * N_CLASSES];
    __shared__ float sb1[HIDDEN];
    for (int i = threadIdx.x; i < HIDDEN * N_CLASSES; i += blockDim.x) sW2[i] = W2[i];
    for (int i = threadIdx.x; i < HIDDEN; i += blockDim.x) sb1[i] = b1[i];
    __syncthreads();

    const int warp = (blockIdx.x * blockDim.x + threadIdx.x) >> 5;
    const int lane = threadIdx.x & 31;
    if (warp >= n) return;

    const int beg = g_off[warp];
    const int end = g_off[warp + 1];
    const float* hrow = g_h + (size_t)warp * HIDDEN;

    // self term
    float4 a0 = *reinterpret_cast<const float4*>(hrow + lane * 4);
    float4 a1 = *reinterpret_cast<const float4*>(hrow + 128 + lane * 4);

    int i = beg;
    for (; i + 1 < end; i += 2) {
        int s0 = __ldg(&g_csr[i]);
        int s1 = __ldg(&g_csr[i + 1]);
        const float* r0 = g_h + (size_t)s0 * HIDDEN;
        const float* r1 = g_h + (size_t)s1 * HIDDEN;
        float4 v00 = *reinterpret_cast<const float4*>(r0 + lane * 4);
        float4 v01 = *reinterpret_cast<const float4*>(r0 + 128 + lane * 4);
        float4 v10 = *reinterpret_cast<const float4*>(r1 + lane * 4);
        float4 v11 = *reinterpret_cast<const float4*>(r1 + 128 + lane * 4);
        a0.x += v00.x + v10.x; a0.y += v00.y + v10.y; a0.z += v00.z + v10.z; a0.w += v00.w + v10.w;
        a1.x += v01.x + v11.x; a1.y += v01.y + v11.y; a1.z += v01.z + v11.z; a1.w += v01.w + v11.w;
    }
    if (i < end) {
        int s0 = __ldg(&g_csr[i]);
        const float* r0 = g_h + (size_t)s0 * HIDDEN;
        float4 v00 = *reinterpret_cast<const float4*>(r0 + lane * 4);
        float4 v01 = *reinterpret_cast<const float4*>(r0 + 128 + lane * 4);
        a0.x += v00.x; a0.y += v00.y; a0.z += v00.z; a0.w += v00.w;
        a1.x += v01.x; a1.y += v01.y; a1.z += v01.z; a1.w += v01.w;
    }

    const float di = g_dinv[warp];
    float acc0 = 0.f, acc1 = 0.f, acc2 = 0.f;
    {
        const int c0 = lane * 4;
        float h;
        h = fmaxf(fmaf(di, a0.x, sb1[c0 + 0]), 0.f);
        acc0 += h * sW2[(c0 + 0) * 3 + 0]; acc1 += h * sW2[(c0 + 0) * 3 + 1]; acc2 += h * sW2[(c0 + 0) * 3 + 2];
        h = fmaxf(fmaf(di, a0.y, sb1[c0 + 1]), 0.f);
        acc0 += h * sW2[(c0 + 1) * 3 + 0]; acc1 += h * sW2[(c0 + 1) * 3 + 1]; acc2 += h * sW2[(c0 + 1) * 3 + 2];
        h = fmaxf(fmaf(di, a0.z, sb1[c0 + 2]), 0.f);
        acc0 += h * sW2[(c0 + 2) * 3 + 0]; acc1 += h * sW2[(c0 + 2) * 3 + 1]; acc2 += h * sW2[(c0 + 2) * 3 + 2];
        h = fmaxf(fmaf(di, a0.w, sb1[c0 + 3]), 0.f);
        acc0 += h * sW2[(c0 + 3) * 3 + 0]; acc1 += h * sW2[(c0 + 3) * 3 + 1]; acc2 += h * sW2[(c0 + 3) * 3 + 2];
        const int c1 = 128 + lane * 4;
        h = fmaxf(fmaf(di, a1.x, sb1[c1 + 0]), 0.f);
        acc0 += h * sW2[(c1 + 0) * 3 + 0]; acc1 += h * sW2[(c1 + 0) * 3 + 1]; acc2 += h * sW2[(c1 + 0) * 3 + 2];
        h = fmaxf(fmaf(di, a1.y, sb1[c1 + 1]), 0.f);
        acc0 += h * sW2[(c1 + 1) * 3 + 0]; acc1 += h * sW2[(c1 + 1) * 3 + 1]; acc2 += h * sW2[(c1 + 1) * 3 + 2];
        h = fmaxf(fmaf(di, a1.z, sb1[c1 + 2]), 0.f);
        acc0 += h * sW2[(c1 + 2) * 3 + 0]; acc1 += h * sW2[(c1 + 2) * 3 + 1]; acc2 += h * sW2[(c1 + 2) * 3 + 2];
        h = fmaxf(fmaf(di, a1.w, sb1[c1 + 3]), 0.f);
        acc0 += h * sW2[(c1 + 3) * 3 + 0]; acc1 += h * sW2[(c1 + 3) * 3 + 1]; acc2 += h * sW2[(c1 + 3) * 3 + 2];
    }
#pragma unroll
    for (int o = 16; o > 0; o >>= 1) {
        acc0 += __shfl_down_sync(0xFFFFFFFFu, acc0, o);
        acc1 += __shfl_down_sync(0xFFFFFFFFu, acc1, o);
        acc2 += __shfl_down_sync(0xFFFFFFFFu, acc2, o);
    }
    if (lane == 0) {
        float l0 = acc0 + b2[0];
        float l1 = acc1 + b2[1];
        float l2 = acc2 + b2[2];
        float m = fmaxf(l0, fmaxf(l1, l2));
        float se = expf(l0 - m) + expf(l1 - m) + expf(l2 - m);
        float lse = m + logf(se);
        out[(size_t)warp * 3 + 0] = l0 - lse;
        out[(size_t)warp * 3 + 1] = l1 - lse;
        out[(size_t)warp * 3 + 2] = l2 - lse;
    }
}

// ---------------------------------------------------------------------------
extern "C" void kernel_launch(void* const* d_in, const int* in_sizes, int n_in,
                              void* d_out, int out_size) {
    const float* x  = (const float*)d_in[0];
    const int*   ei = (const int*)d_in[1];
    const float* W1 = (const float*)d_in[2];
    const float* b1 = (const float*)d_in[3];
    const float* W2 = (const float*)d_in[4];
    const float* b2 = (const float*)d_in[5];
    float* out = (float*)d_out;

    int n = in_sizes[0] / IN_DIM;
    int E = in_sizes[1] / 2;
    const int* src = ei;
    const int* dst = ei + E;

    static int smem_set = 0;
    if (!smem_set) {
        cudaFuncSetAttribute(k_gemm_hmma, cudaFuncAttributeMaxDynamicSharedMemorySize, GEMM_SMEM);
        smem_set = 1;
    }

    // CSR build + degree normalization
    k_zero_cnt<<<(n + 255) / 256, 256>>>(n);
    k_cnt<<<(E + 255) / 256, 256>>>(dst, E);
    k_scan<<<1, 1024>>>(n);
    k_dinv_cur<<<(n + 255) / 256, 256>>>(n);
    k_fill<<<(E + 255) / 256, 256>>>(src, dst, E);

    // W1 split/transpose prep
    k_prep_w1<<<(IN_DIM * HIDDEN + 255) / 256, 256>>>(W1);

    // HMMA GEMM + dinv scale
    dim3 ggrd(HIDDEN / 128, (n + 127) / 128);
    k_gemm_hmma<<<ggrd, 256, GEMM_SMEM>>>(x, n);

    // fused CSR aggregate + finalize (warp per node)
    int fblocks = (n * 32 + 255) / 256;
    k_aggfinal<<<fblocks, 256>>>(b1, W2, b2, out, n);
}